// round 4
// baseline (speedup 1.0000x reference)
#include <cuda_runtime.h>
#include <math.h>

#define Bb  4
#define Nn  2048
#define Ee  512
#define Hh  8
#define HDd 64
#define ATT_SCALE 0.125f   // 64^-0.5

// Scratch (device globals: allocation-guard safe)
__device__ float g_qkv[(size_t)Bb * Nn * 3 * Ee];   // [b][n][3*512] ~50 MB
__device__ float g_ctx[(size_t)Bb * Nn * Ee];       // [b][n][512]   ~17 MB

// ============================================================================
// SGEMM (NT): C[M,N] = A[M,K] * B[N,K]^T + bias[N]
// Tiles 128x128x16, 256 threads, 8x8 per thread, padded transposed smem.
// ============================================================================
#define BM 128
#define BN 128
#define BKK 16

__global__ __launch_bounds__(256) void sgemm_nt_bias(
    const float* __restrict__ A, const float* __restrict__ Bm,
    const float* __restrict__ bias, float* __restrict__ C,
    int M, int N, int K)
{
    __shared__ __align__(16) float As[BKK][BM + 4];
    __shared__ __align__(16) float Bs[BKK][BN + 4];

    const int tid = threadIdx.x;
    const int tx = tid & 15;
    const int ty = tid >> 4;
    const int bm = blockIdx.y * BM;
    const int bn = blockIdx.x * BN;

    const int lrow = tid >> 2;        // 0..63
    const int lk   = (tid & 3) * 4;   // 0,4,8,12

    const float* Ap = A + (size_t)(bm + lrow) * K + lk;
    const float* Bp = Bm + (size_t)(bn + lrow) * K + lk;

    float acc[8][8];
    #pragma unroll
    for (int i = 0; i < 8; i++)
        #pragma unroll
        for (int j = 0; j < 8; j++) acc[i][j] = 0.f;

    for (int k0 = 0; k0 < K; k0 += BKK) {
        float4 a0 = *(const float4*)(Ap + k0);
        float4 a1 = *(const float4*)(Ap + (size_t)64 * K + k0);
        float4 b0 = *(const float4*)(Bp + k0);
        float4 b1 = *(const float4*)(Bp + (size_t)64 * K + k0);

        __syncthreads();
        As[lk + 0][lrow] = a0.x; As[lk + 1][lrow] = a0.y;
        As[lk + 2][lrow] = a0.z; As[lk + 3][lrow] = a0.w;
        As[lk + 0][64 + lrow] = a1.x; As[lk + 1][64 + lrow] = a1.y;
        As[lk + 2][64 + lrow] = a1.z; As[lk + 3][64 + lrow] = a1.w;
        Bs[lk + 0][lrow] = b0.x; Bs[lk + 1][lrow] = b0.y;
        Bs[lk + 2][lrow] = b0.z; Bs[lk + 3][lrow] = b0.w;
        Bs[lk + 0][64 + lrow] = b1.x; Bs[lk + 1][64 + lrow] = b1.y;
        Bs[lk + 2][64 + lrow] = b1.z; Bs[lk + 3][64 + lrow] = b1.w;
        __syncthreads();

        #pragma unroll
        for (int kk = 0; kk < BKK; kk++) {
            float4 x0 = *(const float4*)&As[kk][(ty << 2)];
            float4 x1 = *(const float4*)&As[kk][64 + (ty << 2)];
            float4 y0 = *(const float4*)&Bs[kk][(tx << 2)];
            float4 y1 = *(const float4*)&Bs[kk][64 + (tx << 2)];
            float av[8] = {x0.x, x0.y, x0.z, x0.w, x1.x, x1.y, x1.z, x1.w};
            float bv[8] = {y0.x, y0.y, y0.z, y0.w, y1.x, y1.y, y1.z, y1.w};
            #pragma unroll
            for (int i = 0; i < 8; i++)
                #pragma unroll
                for (int j = 0; j < 8; j++)
                    acc[i][j] = fmaf(av[i], bv[j], acc[i][j]);
        }
    }

    float4 bias0 = *(const float4*)(bias + bn + (tx << 2));
    float4 bias1 = *(const float4*)(bias + bn + 64 + (tx << 2));

    #pragma unroll
    for (int i = 0; i < 8; i++) {
        int m = bm + ((i < 4) ? ((ty << 2) + i) : (64 + (ty << 2) + i - 4));
        float* cp = C + (size_t)m * N + bn;
        float4 r0 = make_float4(acc[i][0] + bias0.x, acc[i][1] + bias0.y,
                                acc[i][2] + bias0.z, acc[i][3] + bias0.w);
        float4 r1 = make_float4(acc[i][4] + bias1.x, acc[i][5] + bias1.y,
                                acc[i][6] + bias1.z, acc[i][7] + bias1.w);
        *(float4*)(cp + (tx << 2)) = r0;
        *(float4*)(cp + 64 + (tx << 2)) = r1;
    }
}

// ============================================================================
// Flash attention fp32.
// grid = (Nn/64, B*H), 256 threads. CTA handles one (b,h) and 64 queries.
// smem: Qs[d][q] (transposed, scaled), Ks[d][k] (transposed), Vs[k][d], Ss[q][k]
// all with row stride 68 for bank safety; alpha/l per row.
// ============================================================================
#define AT_STRIDE 68
#define AT_TILEF  (64 * AT_STRIDE)
#define ATT_SMEM_BYTES ((4 * AT_TILEF + 128) * 4)

__global__ __launch_bounds__(256) void attn_kernel()
{
    extern __shared__ __align__(16) float sm[];
    float* Qs = sm;
    float* Ks = sm + AT_TILEF;
    float* Vs = sm + 2 * AT_TILEF;
    float* Ss = sm + 3 * AT_TILEF;
    float* alphaS = sm + 4 * AT_TILEF;  // [64]
    float* lS     = alphaS + 64;        // [64]

    const int tid = threadIdx.x;
    const int tx = tid & 15;
    const int ty = tid >> 4;
    const int bh = blockIdx.y;
    const int b = bh >> 3;
    const int h = bh & 7;
    const int q0 = blockIdx.x * 64;

    const float* qbase = g_qkv + (size_t)b * Nn * 1536 + h * 64;
    const float* kbase = qbase + 512;
    const float* vbase = qbase + 1024;

    const int lrow = tid >> 2;         // 0..63
    const int lseg = (tid & 3) * 16;   // 0,16,32,48

    // Load Q tile: scaled + transposed -> Qs[d][q]
    {
        const float* qp = qbase + (size_t)(q0 + lrow) * 1536 + lseg;
        #pragma unroll
        for (int u = 0; u < 4; u++) {
            float4 v = *(const float4*)(qp + u * 4);
            Qs[(lseg + u * 4 + 0) * AT_STRIDE + lrow] = v.x * ATT_SCALE;
            Qs[(lseg + u * 4 + 1) * AT_STRIDE + lrow] = v.y * ATT_SCALE;
            Qs[(lseg + u * 4 + 2) * AT_STRIDE + lrow] = v.z * ATT_SCALE;
            Qs[(lseg + u * 4 + 3) * AT_STRIDE + lrow] = v.w * ATT_SCALE;
        }
    }

    float o[4][4];
    #pragma unroll
    for (int i = 0; i < 4; i++)
        #pragma unroll
        for (int j = 0; j < 4; j++) o[i][j] = 0.f;

    float m_prev = -1e30f;
    float lsum = 0.f;
    const int r = tid >> 2;   // softmax row
    const int g = tid & 3;    // softmax lane-in-group

    for (int kt = 0; kt < Nn; kt += 64) {
        __syncthreads();  // previous PV done (and Q load visible on iter 0 via next sync)

        // Load K transposed, V natural
        {
            const float* kp = kbase + (size_t)(kt + lrow) * 1536 + lseg;
            #pragma unroll
            for (int u = 0; u < 4; u++) {
                float4 v = *(const float4*)(kp + u * 4);
                Ks[(lseg + u * 4 + 0) * AT_STRIDE + lrow] = v.x;
                Ks[(lseg + u * 4 + 1) * AT_STRIDE + lrow] = v.y;
                Ks[(lseg + u * 4 + 2) * AT_STRIDE + lrow] = v.z;
                Ks[(lseg + u * 4 + 3) * AT_STRIDE + lrow] = v.w;
            }
            const float* vp = vbase + (size_t)(kt + lrow) * 1536 + lseg;
            #pragma unroll
            for (int u = 0; u < 4; u++) {
                float4 v = *(const float4*)(vp + u * 4);
                *(float4*)&Vs[lrow * AT_STRIDE + lseg + u * 4] = v;
            }
        }
        __syncthreads();

        // S[q][k] = (Q*scale) . K, 4x4 per thread
        float acc[4][4];
        #pragma unroll
        for (int i = 0; i < 4; i++)
            #pragma unroll
            for (int j = 0; j < 4; j++) acc[i][j] = 0.f;

        #pragma unroll 16
        for (int dd = 0; dd < 64; dd++) {
            float4 aq = *(const float4*)&Qs[dd * AT_STRIDE + (ty << 2)];
            float4 bk = *(const float4*)&Ks[dd * AT_STRIDE + (tx << 2)];
            acc[0][0] = fmaf(aq.x, bk.x, acc[0][0]);
            acc[0][1] = fmaf(aq.x, bk.y, acc[0][1]);
            acc[0][2] = fmaf(aq.x, bk.z, acc[0][2]);
            acc[0][3] = fmaf(aq.x, bk.w, acc[0][3]);
            acc[1][0] = fmaf(aq.y, bk.x, acc[1][0]);
            acc[1][1] = fmaf(aq.y, bk.y, acc[1][1]);
            acc[1][2] = fmaf(aq.y, bk.z, acc[1][2]);
            acc[1][3] = fmaf(aq.y, bk.w, acc[1][3]);
            acc[2][0] = fmaf(aq.z, bk.x, acc[2][0]);
            acc[2][1] = fmaf(aq.z, bk.y, acc[2][1]);
            acc[2][2] = fmaf(aq.z, bk.z, acc[2][2]);
            acc[2][3] = fmaf(aq.z, bk.w, acc[2][3]);
            acc[3][0] = fmaf(aq.w, bk.x, acc[3][0]);
            acc[3][1] = fmaf(aq.w, bk.y, acc[3][1]);
            acc[3][2] = fmaf(aq.w, bk.z, acc[3][2]);
            acc[3][3] = fmaf(aq.w, bk.w, acc[3][3]);
        }
        #pragma unroll
        for (int i = 0; i < 4; i++) {
            *(float4*)&Ss[((ty << 2) + i) * AT_STRIDE + (tx << 2)] =
                make_float4(acc[i][0], acc[i][1], acc[i][2], acc[i][3]);
        }
        __syncthreads();

        // Online softmax: 4 lanes per row, 16 cols each
        {
            float* srow = Ss + r * AT_STRIDE + g * 16;
            float4 s0 = *(float4*)(srow + 0);
            float4 s1 = *(float4*)(srow + 4);
            float4 s2 = *(float4*)(srow + 8);
            float4 s3 = *(float4*)(srow + 12);
            float mx = fmaxf(fmaxf(fmaxf(s0.x, s0.y), fmaxf(s0.z, s0.w)),
                             fmaxf(fmaxf(s1.x, s1.y), fmaxf(s1.z, s1.w)));
            mx = fmaxf(mx, fmaxf(fmaxf(fmaxf(s2.x, s2.y), fmaxf(s2.z, s2.w)),
                                 fmaxf(fmaxf(s3.x, s3.y), fmaxf(s3.z, s3.w))));
            mx = fmaxf(mx, __shfl_xor_sync(0xffffffffu, mx, 1));
            mx = fmaxf(mx, __shfl_xor_sync(0xffffffffu, mx, 2));
            float m_new = fmaxf(m_prev, mx);

            s0.x = __expf(s0.x - m_new); s0.y = __expf(s0.y - m_new);
            s0.z = __expf(s0.z - m_new); s0.w = __expf(s0.w - m_new);
            s1.x = __expf(s1.x - m_new); s1.y = __expf(s1.y - m_new);
            s1.z = __expf(s1.z - m_new); s1.w = __expf(s1.w - m_new);
            s2.x = __expf(s2.x - m_new); s2.y = __expf(s2.y - m_new);
            s2.z = __expf(s2.z - m_new); s2.w = __expf(s2.w - m_new);
            s3.x = __expf(s3.x - m_new); s3.y = __expf(s3.y - m_new);
            s3.z = __expf(s3.z - m_new); s3.w = __expf(s3.w - m_new);

            float ssum = (s0.x + s0.y + s0.z + s0.w) + (s1.x + s1.y + s1.z + s1.w)
                       + (s2.x + s2.y + s2.z + s2.w) + (s3.x + s3.y + s3.z + s3.w);
            ssum += __shfl_xor_sync(0xffffffffu, ssum, 1);
            ssum += __shfl_xor_sync(0xffffffffu, ssum, 2);

            float alpha = __expf(m_prev - m_new);
            lsum = lsum * alpha + ssum;
            m_prev = m_new;

            *(float4*)(srow + 0) = s0;
            *(float4*)(srow + 4) = s1;
            *(float4*)(srow + 8) = s2;
            *(float4*)(srow + 12) = s3;
            if (g == 0) alphaS[r] = alpha;
        }
        __syncthreads();

        // O = O*alpha + P @ V
        {
            float al0 = alphaS[(ty << 2) + 0];
            float al1 = alphaS[(ty << 2) + 1];
            float al2 = alphaS[(ty << 2) + 2];
            float al3 = alphaS[(ty << 2) + 3];
            #pragma unroll
            for (int j = 0; j < 4; j++) {
                o[0][j] *= al0; o[1][j] *= al1; o[2][j] *= al2; o[3][j] *= al3;
            }

            #pragma unroll
            for (int k0 = 0; k0 < 64; k0 += 4) {
                float4 pa0 = *(const float4*)&Ss[((ty << 2) + 0) * AT_STRIDE + k0];
                float4 pa1 = *(const float4*)&Ss[((ty << 2) + 1) * AT_STRIDE + k0];
                float4 pa2 = *(const float4*)&Ss[((ty << 2) + 2) * AT_STRIDE + k0];
                float4 pa3 = *(const float4*)&Ss[((ty << 2) + 3) * AT_STRIDE + k0];

                #define PV_STEP(U, COMP)                                              \
                {                                                                     \
                    float4 vv = *(const float4*)&Vs[(k0 + U) * AT_STRIDE + (tx << 2)];\
                    o[0][0] = fmaf(pa0.COMP, vv.x, o[0][0]);                          \
                    o[0][1] = fmaf(pa0.COMP, vv.y, o[0][1]);                          \
                    o[0][2] = fmaf(pa0.COMP, vv.z, o[0][2]);                          \
                    o[0][3] = fmaf(pa0.COMP, vv.w, o[0][3]);                          \
                    o[1][0] = fmaf(pa1.COMP, vv.x, o[1][0]);                          \
                    o[1][1] = fmaf(pa1.COMP, vv.y, o[1][1]);                          \
                    o[1][2] = fmaf(pa1.COMP, vv.z, o[1][2]);                          \
                    o[1][3] = fmaf(pa1.COMP, vv.w, o[1][3]);                          \
                    o[2][0] = fmaf(pa2.COMP, vv.x, o[2][0]);                          \
                    o[2][1] = fmaf(pa2.COMP, vv.y, o[2][1]);                          \
                    o[2][2] = fmaf(pa2.COMP, vv.z, o[2][2]);                          \
                    o[2][3] = fmaf(pa2.COMP, vv.w, o[2][3]);                          \
                    o[3][0] = fmaf(pa3.COMP, vv.x, o[3][0]);                          \
                    o[3][1] = fmaf(pa3.COMP, vv.y, o[3][1]);                          \
                    o[3][2] = fmaf(pa3.COMP, vv.z, o[3][2]);                          \
                    o[3][3] = fmaf(pa3.COMP, vv.w, o[3][3]);                          \
                }
                PV_STEP(0, x)
                PV_STEP(1, y)
                PV_STEP(2, z)
                PV_STEP(3, w)
                #undef PV_STEP
            }
        }
    }

    if (g == 0) lS[r] = lsum;
    __syncthreads();

    float inv0 = 1.0f / lS[(ty << 2) + 0];
    float inv1 = 1.0f / lS[(ty << 2) + 1];
    float inv2 = 1.0f / lS[(ty << 2) + 2];
    float inv3 = 1.0f / lS[(ty << 2) + 3];

    float* cbase = g_ctx + ((size_t)b * Nn + q0) * Ee + h * 64 + (tx << 2);
    *(float4*)(cbase + (size_t)((ty << 2) + 0) * Ee) =
        make_float4(o[0][0] * inv0, o[0][1] * inv0, o[0][2] * inv0, o[0][3] * inv0);
    *(float4*)(cbase + (size_t)((ty << 2) + 1) * Ee) =
        make_float4(o[1][0] * inv1, o[1][1] * inv1, o[1][2] * inv1, o[1][3] * inv1);
    *(float4*)(cbase + (size_t)((ty << 2) + 2) * Ee) =
        make_float4(o[2][0] * inv2, o[2][1] * inv2, o[2][2] * inv2, o[2][3] * inv2);
    *(float4*)(cbase + (size_t)((ty << 2) + 3) * Ee) =
        make_float4(o[3][0] * inv3, o[3][1] * inv3, o[3][2] * inv3, o[3][3] * inv3);
}

// ============================================================================
// Host launch
// ============================================================================
extern "C" void kernel_launch(void* const* d_in, const int* in_sizes, int n_in,
                              void* d_out, int out_size)
{
    const float* x     = (const float*)d_in[0];
    const float* w_qkv = (const float*)d_in[1];
    const float* b_qkv = (const float*)d_in[2];
    const float* w_out = (const float*)d_in[3];
    const float* b_out = (const float*)d_in[4];
    float* out = (float*)d_out;

    void* qkv_ptr = nullptr;
    void* ctx_ptr = nullptr;
    cudaGetSymbolAddress(&qkv_ptr, g_qkv);
    cudaGetSymbolAddress(&ctx_ptr, g_ctx);
    float* qkv = (float*)qkv_ptr;
    float* ctx = (float*)ctx_ptr;

    cudaFuncSetAttribute(attn_kernel, cudaFuncAttributeMaxDynamicSharedMemorySize,
                         ATT_SMEM_BYTES);

    const int M = Bb * Nn;  // 8192

    // 1) QKV projection: [8192,1536] = x[8192,512] @ w_qkv[1536,512]^T + b_qkv
    sgemm_nt_bias<<<dim3(3 * Ee / BN, M / BM), 256>>>(x, w_qkv, b_qkv, qkv,
                                                      M, 3 * Ee, Ee);

    // 2) Attention: per (b,h), 64-query tiles
    attn_kernel<<<dim3(Nn / 64, Bb * Hh), 256, ATT_SMEM_BYTES>>>();

    // 3) Output projection: out[8192,512] = ctx[8192,512] @ w_out[512,512]^T + b_out
    sgemm_nt_bias<<<dim3(Ee / BN, M / BM), 256>>>(ctx, w_out, b_out, out,
                                                  M, Ee, Ee);
}

// round 6
// speedup vs baseline: 1.4906x; 1.4906x over previous
#include <cuda_runtime.h>
#include <math.h>

#define Bb  4
#define Nn  2048
#define Ee  512
#define Hh  8
#define ATT_SCALE 0.125f   // 64^-0.5

// Scratch (device globals: allocation-guard safe)
__device__ float g_qkv[(size_t)Bb * Nn * 3 * Ee];   // ~50 MB
__device__ float g_ctx[(size_t)Bb * Nn * Ee];       // ~17 MB

// ---------------------------------------------------------------------------
// TF32 helpers
// ---------------------------------------------------------------------------
__device__ __forceinline__ float f2tf(float x) {
    unsigned r;
    asm("cvt.rna.tf32.f32 %0, %1;" : "=r"(r) : "f"(x));
    return __uint_as_float(r);
}

__device__ __forceinline__ void mma_tf32(float c[4],
                                         float a0, float a1, float a2, float a3,
                                         float b0, float b1) {
    asm volatile(
        "mma.sync.aligned.m16n8k8.row.col.f32.tf32.tf32.f32 "
        "{%0,%1,%2,%3}, {%4,%5,%6,%7}, {%8,%9}, {%0,%1,%2,%3};"
        : "+f"(c[0]), "+f"(c[1]), "+f"(c[2]), "+f"(c[3])
        : "r"(__float_as_uint(a0)), "r"(__float_as_uint(a1)),
          "r"(__float_as_uint(a2)), "r"(__float_as_uint(a3)),
          "r"(__float_as_uint(b0)), "r"(__float_as_uint(b1)));
}

// ============================================================================
// TF32 GEMM (NT): C[M,N] = A[M,K] * B[N,K]^T + bias[N]
// 128x128x32 tiles, 256 threads (8 warps), warp = m32 x n64.
// smem stride 36 (== 4 mod 32) -> conflict-free fragment LDS.
// ============================================================================
#define GSTR 36

__global__ __launch_bounds__(256) void gemm_tf32(
    const float* __restrict__ A, const float* __restrict__ Bm,
    const float* __restrict__ bias, float* __restrict__ C,
    int M, int N, int K)
{
    __shared__ __align__(16) float As[128][GSTR];
    __shared__ __align__(16) float Bs[128][GSTR];

    const int tid  = threadIdx.x;
    const int warp = tid >> 5, lane = tid & 31;
    const int grp  = lane >> 2, tig = lane & 3;
    const int bm = blockIdx.y * 128, bn = blockIdx.x * 128;
    const int wm = (warp & 3) * 32, wn = (warp >> 2) * 64;

    float acc[2][8][4];
    #pragma unroll
    for (int mt = 0; mt < 2; mt++)
        #pragma unroll
        for (int nt = 0; nt < 8; nt++)
            #pragma unroll
            for (int i = 0; i < 4; i++) acc[mt][nt][i] = 0.f;

    const int ldr = tid >> 3;        // 0..31 base row
    const int ldc = (tid & 7) * 4;   // col 0..28 step 4

    for (int kt = 0; kt < K; kt += 32) {
        __syncthreads();
        #pragma unroll
        for (int i = 0; i < 4; i++) {
            int r = ldr + i * 32;
            float4 va = *(const float4*)(A + (size_t)(bm + r) * K + kt + ldc);
            *(float4*)&As[r][ldc] =
                make_float4(f2tf(va.x), f2tf(va.y), f2tf(va.z), f2tf(va.w));
            float4 vb = *(const float4*)(Bm + (size_t)(bn + r) * K + kt + ldc);
            *(float4*)&Bs[r][ldc] =
                make_float4(f2tf(vb.x), f2tf(vb.y), f2tf(vb.z), f2tf(vb.w));
        }
        __syncthreads();

        #pragma unroll
        for (int ks = 0; ks < 32; ks += 8) {
            float a[2][4];
            #pragma unroll
            for (int mt = 0; mt < 2; mt++) {
                a[mt][0] = As[wm + mt * 16 + grp][ks + tig];
                a[mt][1] = As[wm + mt * 16 + grp + 8][ks + tig];
                a[mt][2] = As[wm + mt * 16 + grp][ks + tig + 4];
                a[mt][3] = As[wm + mt * 16 + grp + 8][ks + tig + 4];
            }
            #pragma unroll
            for (int nt = 0; nt < 8; nt++) {
                float b0 = Bs[wn + nt * 8 + grp][ks + tig];
                float b1 = Bs[wn + nt * 8 + grp][ks + tig + 4];
                mma_tf32(acc[0][nt], a[0][0], a[0][1], a[0][2], a[0][3], b0, b1);
                mma_tf32(acc[1][nt], a[1][0], a[1][1], a[1][2], a[1][3], b0, b1);
            }
        }
    }

    #pragma unroll
    for (int nt = 0; nt < 8; nt++) {
        int col = bn + wn + nt * 8 + tig * 2;
        float2 bv = *(const float2*)(bias + col);
        #pragma unroll
        for (int mt = 0; mt < 2; mt++) {
            int r0 = bm + wm + mt * 16 + grp;
            *(float2*)(C + (size_t)r0 * N + col) =
                make_float2(acc[mt][nt][0] + bv.x, acc[mt][nt][1] + bv.y);
            *(float2*)(C + (size_t)(r0 + 8) * N + col) =
                make_float2(acc[mt][nt][2] + bv.x, acc[mt][nt][3] + bv.y);
        }
    }
}

// ============================================================================
// Flash attention, TF32 tensor-core MMA.
// grid = (Nn/64, B*H), 256 threads (8 warps).
// Warp w: q-rows [16*(w&3), +16), cols (key or d) [32*(w>>2), +32).
// Qs/Ks/Ss stride 68 (==4 mod 32), Vs stride 72 (==8 mod 32).
// ============================================================================
#define QS     68
#define VSTR   72
#define ATT_SMEM_BYTES ((3 * 64 * QS + 64 * VSTR + 128) * 4)

__global__ __launch_bounds__(256) void attn_tf32()
{
    extern __shared__ __align__(16) float sm[];
    float* Qs = sm;                         // [64][68]
    float* Ks = sm + 64 * QS;               // [64][68]
    float* Ss = sm + 2 * 64 * QS;           // [64][68]
    float* Vs = sm + 3 * 64 * QS;           // [64][72]
    float* alphaS = sm + 3 * 64 * QS + 64 * VSTR;  // [64]
    float* lS     = alphaS + 64;                   // [64]

    const int tid  = threadIdx.x;
    const int warp = tid >> 5, lane = tid & 31;
    const int grp  = lane >> 2, tig = lane & 3;
    const int wm = (warp & 3) * 16, wn = (warp >> 2) * 32;

    const int bh = blockIdx.y;
    const int b = bh >> 3, h = bh & 7;
    const int q0 = blockIdx.x * 64;

    const float* qbase = g_qkv + (size_t)b * Nn * 1536 + h * 64;
    const float* kbase = qbase + 512;
    const float* vbase = qbase + 1024;

    const int lrow = tid >> 2;          // 0..63
    const int lseg = (tid & 3) * 16;    // 0,16,32,48

    // Load Q tile (scaled, tf32-rounded), natural [q][d]
    {
        const float* qp = qbase + (size_t)(q0 + lrow) * 1536 + lseg;
        #pragma unroll
        for (int u = 0; u < 4; u++) {
            float4 v = *(const float4*)(qp + u * 4);
            *(float4*)&Qs[lrow * QS + lseg + u * 4] = make_float4(
                f2tf(v.x * ATT_SCALE), f2tf(v.y * ATT_SCALE),
                f2tf(v.z * ATT_SCALE), f2tf(v.w * ATT_SCALE));
        }
    }

    float o[4][4];
    #pragma unroll
    for (int nt = 0; nt < 4; nt++)
        #pragma unroll
        for (int i = 0; i < 4; i++) o[nt][i] = 0.f;

    float m_prev = -1e30f, lsum = 0.f;
    const int r = tid >> 2;   // softmax row
    const int g = tid & 3;    // softmax lane-in-group

    for (int kt = 0; kt < Nn; kt += 64) {
        __syncthreads();   // previous PV reads done; Q visible (iter 0)

        // Load K and V tiles (tf32-rounded)
        {
            const float* kp = kbase + (size_t)(kt + lrow) * 1536 + lseg;
            #pragma unroll
            for (int u = 0; u < 4; u++) {
                float4 v = *(const float4*)(kp + u * 4);
                *(float4*)&Ks[lrow * QS + lseg + u * 4] =
                    make_float4(f2tf(v.x), f2tf(v.y), f2tf(v.z), f2tf(v.w));
            }
            const float* vp = vbase + (size_t)(kt + lrow) * 1536 + lseg;
            #pragma unroll
            for (int u = 0; u < 4; u++) {
                float4 v = *(const float4*)(vp + u * 4);
                *(float4*)&Vs[lrow * VSTR + lseg + u * 4] =
                    make_float4(f2tf(v.x), f2tf(v.y), f2tf(v.z), f2tf(v.w));
            }
        }
        __syncthreads();

        // S = Q K^T  (warp: m16 x n32, k=64)
        float sc[4][4];
        #pragma unroll
        for (int nt = 0; nt < 4; nt++)
            #pragma unroll
            for (int i = 0; i < 4; i++) sc[nt][i] = 0.f;

        #pragma unroll
        for (int ks = 0; ks < 64; ks += 8) {
            float a0 = Qs[(wm + grp) * QS + ks + tig];
            float a1 = Qs[(wm + grp + 8) * QS + ks + tig];
            float a2 = Qs[(wm + grp) * QS + ks + tig + 4];
            float a3 = Qs[(wm + grp + 8) * QS + ks + tig + 4];
            #pragma unroll
            for (int nt = 0; nt < 4; nt++) {
                float b0 = Ks[(wn + nt * 8 + grp) * QS + ks + tig];
                float b1 = Ks[(wn + nt * 8 + grp) * QS + ks + tig + 4];
                mma_tf32(sc[nt], a0, a1, a2, a3, b0, b1);
            }
        }
        #pragma unroll
        for (int nt = 0; nt < 4; nt++) {
            *(float2*)&Ss[(wm + grp) * QS + wn + nt * 8 + tig * 2] =
                make_float2(sc[nt][0], sc[nt][1]);
            *(float2*)&Ss[(wm + grp + 8) * QS + wn + nt * 8 + tig * 2] =
                make_float2(sc[nt][2], sc[nt][3]);
        }
        __syncthreads();

        // Online softmax (4 lanes per row, 16 cols each); store exp as tf32
        {
            float* srow = Ss + r * QS + g * 16;
            float4 s0 = *(float4*)(srow + 0);
            float4 s1 = *(float4*)(srow + 4);
            float4 s2 = *(float4*)(srow + 8);
            float4 s3 = *(float4*)(srow + 12);
            float mx = fmaxf(fmaxf(fmaxf(s0.x, s0.y), fmaxf(s0.z, s0.w)),
                             fmaxf(fmaxf(s1.x, s1.y), fmaxf(s1.z, s1.w)));
            mx = fmaxf(mx, fmaxf(fmaxf(fmaxf(s2.x, s2.y), fmaxf(s2.z, s2.w)),
                                 fmaxf(fmaxf(s3.x, s3.y), fmaxf(s3.z, s3.w))));
            mx = fmaxf(mx, __shfl_xor_sync(0xffffffffu, mx, 1));
            mx = fmaxf(mx, __shfl_xor_sync(0xffffffffu, mx, 2));
            float m_new = fmaxf(m_prev, mx);

            s0.x = __expf(s0.x - m_new); s0.y = __expf(s0.y - m_new);
            s0.z = __expf(s0.z - m_new); s0.w = __expf(s0.w - m_new);
            s1.x = __expf(s1.x - m_new); s1.y = __expf(s1.y - m_new);
            s1.z = __expf(s1.z - m_new); s1.w = __expf(s1.w - m_new);
            s2.x = __expf(s2.x - m_new); s2.y = __expf(s2.y - m_new);
            s2.z = __expf(s2.z - m_new); s2.w = __expf(s2.w - m_new);
            s3.x = __expf(s3.x - m_new); s3.y = __expf(s3.y - m_new);
            s3.z = __expf(s3.z - m_new); s3.w = __expf(s3.w - m_new);

            float ssum = (s0.x + s0.y + s0.z + s0.w) + (s1.x + s1.y + s1.z + s1.w)
                       + (s2.x + s2.y + s2.z + s2.w) + (s3.x + s3.y + s3.z + s3.w);
            ssum += __shfl_xor_sync(0xffffffffu, ssum, 1);
            ssum += __shfl_xor_sync(0xffffffffu, ssum, 2);

            float alpha = __expf(m_prev - m_new);
            lsum = lsum * alpha + ssum;
            m_prev = m_new;

            *(float4*)(srow + 0)  = make_float4(f2tf(s0.x), f2tf(s0.y), f2tf(s0.z), f2tf(s0.w));
            *(float4*)(srow + 4)  = make_float4(f2tf(s1.x), f2tf(s1.y), f2tf(s1.z), f2tf(s1.w));
            *(float4*)(srow + 8)  = make_float4(f2tf(s2.x), f2tf(s2.y), f2tf(s2.z), f2tf(s2.w));
            *(float4*)(srow + 12) = make_float4(f2tf(s3.x), f2tf(s3.y), f2tf(s3.z), f2tf(s3.w));
            if (g == 0) alphaS[r] = alpha;
        }
        __syncthreads();

        // O = O*alpha + P @ V  (warp: m16 x n32 over d, k=64 keys)
        {
            float al_a = alphaS[wm + grp];
            float al_b = alphaS[wm + grp + 8];
            #pragma unroll
            for (int nt = 0; nt < 4; nt++) {
                o[nt][0] *= al_a; o[nt][1] *= al_a;
                o[nt][2] *= al_b; o[nt][3] *= al_b;
            }
            #pragma unroll
            for (int ks = 0; ks < 64; ks += 8) {
                float a0 = Ss[(wm + grp) * QS + ks + tig];
                float a1 = Ss[(wm + grp + 8) * QS + ks + tig];
                float a2 = Ss[(wm + grp) * QS + ks + tig + 4];
                float a3 = Ss[(wm + grp + 8) * QS + ks + tig + 4];
                #pragma unroll
                for (int nt = 0; nt < 4; nt++) {
                    float b0 = Vs[(ks + tig) * VSTR + wn + nt * 8 + grp];
                    float b1 = Vs[(ks + tig + 4) * VSTR + wn + nt * 8 + grp];
                    mma_tf32(o[nt], a0, a1, a2, a3, b0, b1);
                }
            }
        }
    }

    if (g == 0) lS[r] = lsum;
    __syncthreads();

    float inv_a = 1.0f / lS[wm + grp];
    float inv_b = 1.0f / lS[wm + grp + 8];

    #pragma unroll
    for (int nt = 0; nt < 4; nt++) {
        int col = h * 64 + wn + nt * 8 + tig * 2;
        float* c0 = g_ctx + ((size_t)b * Nn + q0 + wm + grp) * Ee + col;
        *(float2*)c0 = make_float2(o[nt][0] * inv_a, o[nt][1] * inv_a);
        float* c1 = g_ctx + ((size_t)b * Nn + q0 + wm + grp + 8) * Ee + col;
        *(float2*)c1 = make_float2(o[nt][2] * inv_b, o[nt][3] * inv_b);
    }
}

// ============================================================================
// Host launch
// ============================================================================
extern "C" void kernel_launch(void* const* d_in, const int* in_sizes, int n_in,
                              void* d_out, int out_size)
{
    const float* x     = (const float*)d_in[0];
    const float* w_qkv = (const float*)d_in[1];
    const float* b_qkv = (const float*)d_in[2];
    const float* w_out = (const float*)d_in[3];
    const float* b_out = (const float*)d_in[4];
    float* out = (float*)d_out;

    void* qkv_ptr = nullptr;
    void* ctx_ptr = nullptr;
    cudaGetSymbolAddress(&qkv_ptr, g_qkv);
    cudaGetSymbolAddress(&ctx_ptr, g_ctx);
    float* qkv = (float*)qkv_ptr;
    float* ctx = (float*)ctx_ptr;

    cudaFuncSetAttribute(attn_tf32, cudaFuncAttributeMaxDynamicSharedMemorySize,
                         ATT_SMEM_BYTES);

    const int M = Bb * Nn;  // 8192

    // 1) QKV projection: [8192,1536] = x[8192,512] @ w_qkv[1536,512]^T + b_qkv
    gemm_tf32<<<dim3(3 * Ee / 128, M / 128), 256>>>(x, w_qkv, b_qkv, qkv,
                                                    M, 3 * Ee, Ee);

    // 2) Attention
    attn_tf32<<<dim3(Nn / 64, Bb * Hh), 256, ATT_SMEM_BYTES>>>();

    // 3) Output projection: out[8192,512] = ctx[8192,512] @ w_out[512,512]^T + b_out
    gemm_tf32<<<dim3(Ee / 128, M / 128), 256>>>(ctx, w_out, b_out, out,
                                                M, Ee, Ee);
}

// round 7
// speedup vs baseline: 3.0096x; 2.0190x over previous
#include <cuda_runtime.h>
#include <math.h>

#define Bb  4
#define Nn  2048
#define Ee  512
#define Hh  8
#define ATT_SCALE 0.125f   // 64^-0.5

// Scratch (device globals: allocation-guard safe)
__device__ float g_qkv[(size_t)Bb * Nn * 3 * Ee];   // ~50 MB
__device__ float g_ctx[(size_t)Bb * Nn * Ee];       // ~17 MB

// ---------------------------------------------------------------------------
// TF32 helpers
// ---------------------------------------------------------------------------
__device__ __forceinline__ float f2tf(float x) {
    unsigned r;
    asm("cvt.rna.tf32.f32 %0, %1;" : "=r"(r) : "f"(x));
    return __uint_as_float(r);
}

__device__ __forceinline__ void mma_tf32(float c[4],
                                         float a0, float a1, float a2, float a3,
                                         float b0, float b1) {
    asm volatile(
        "mma.sync.aligned.m16n8k8.row.col.f32.tf32.tf32.f32 "
        "{%0,%1,%2,%3}, {%4,%5,%6,%7}, {%8,%9}, {%0,%1,%2,%3};"
        : "+f"(c[0]), "+f"(c[1]), "+f"(c[2]), "+f"(c[3])
        : "r"(__float_as_uint(a0)), "r"(__float_as_uint(a1)),
          "r"(__float_as_uint(a2)), "r"(__float_as_uint(a3)),
          "r"(__float_as_uint(b0)), "r"(__float_as_uint(b1)));
}

// ============================================================================
// TF32 GEMM (NT): C[M,N] = A[M,K] * B[N,K]^T + bias[N]   (unchanged from R5)
// ============================================================================
#define GSTR 36

__global__ __launch_bounds__(256) void gemm_tf32(
    const float* __restrict__ A, const float* __restrict__ Bm,
    const float* __restrict__ bias, float* __restrict__ C,
    int M, int N, int K)
{
    __shared__ __align__(16) float As[128][GSTR];
    __shared__ __align__(16) float Bs[128][GSTR];

    const int tid  = threadIdx.x;
    const int warp = tid >> 5, lane = tid & 31;
    const int grp  = lane >> 2, tig = lane & 3;
    const int bm = blockIdx.y * 128, bn = blockIdx.x * 128;
    const int wm = (warp & 3) * 32, wn = (warp >> 2) * 64;

    float acc[2][8][4];
    #pragma unroll
    for (int mt = 0; mt < 2; mt++)
        #pragma unroll
        for (int nt = 0; nt < 8; nt++)
            #pragma unroll
            for (int i = 0; i < 4; i++) acc[mt][nt][i] = 0.f;

    const int ldr = tid >> 3;
    const int ldc = (tid & 7) * 4;

    for (int kt = 0; kt < K; kt += 32) {
        __syncthreads();
        #pragma unroll
        for (int i = 0; i < 4; i++) {
            int r = ldr + i * 32;
            float4 va = *(const float4*)(A + (size_t)(bm + r) * K + kt + ldc);
            *(float4*)&As[r][ldc] =
                make_float4(f2tf(va.x), f2tf(va.y), f2tf(va.z), f2tf(va.w));
            float4 vb = *(const float4*)(Bm + (size_t)(bn + r) * K + kt + ldc);
            *(float4*)&Bs[r][ldc] =
                make_float4(f2tf(vb.x), f2tf(vb.y), f2tf(vb.z), f2tf(vb.w));
        }
        __syncthreads();

        #pragma unroll
        for (int ks = 0; ks < 32; ks += 8) {
            float a[2][4];
            #pragma unroll
            for (int mt = 0; mt < 2; mt++) {
                a[mt][0] = As[wm + mt * 16 + grp][ks + tig];
                a[mt][1] = As[wm + mt * 16 + grp + 8][ks + tig];
                a[mt][2] = As[wm + mt * 16 + grp][ks + tig + 4];
                a[mt][3] = As[wm + mt * 16 + grp + 8][ks + tig + 4];
            }
            #pragma unroll
            for (int nt = 0; nt < 8; nt++) {
                float b0 = Bs[wn + nt * 8 + grp][ks + tig];
                float b1 = Bs[wn + nt * 8 + grp][ks + tig + 4];
                mma_tf32(acc[0][nt], a[0][0], a[0][1], a[0][2], a[0][3], b0, b1);
                mma_tf32(acc[1][nt], a[1][0], a[1][1], a[1][2], a[1][3], b0, b1);
            }
        }
    }

    #pragma unroll
    for (int nt = 0; nt < 8; nt++) {
        int col = bn + wn + nt * 8 + tig * 2;
        float2 bv = *(const float2*)(bias + col);
        #pragma unroll
        for (int mt = 0; mt < 2; mt++) {
            int r0 = bm + wm + mt * 16 + grp;
            *(float2*)(C + (size_t)r0 * N + col) =
                make_float2(acc[mt][nt][0] + bv.x, acc[mt][nt][1] + bv.y);
            *(float2*)(C + (size_t)(r0 + 8) * N + col) =
                make_float2(acc[mt][nt][2] + bv.x, acc[mt][nt][3] + bv.y);
        }
    }
}

// ============================================================================
// Flash attention v2: 128 queries/CTA, 8 warps each m16 x n64.
// S and softmax fully in registers; Q in register fragments.
// smem: Ks[64][68], Vs[64][72], Ps[128][68] (also Q staging) = ~69 KB.
// ============================================================================
#define KSTR 68
#define VSTR 72
#define PSTR 68
#define ATT_SMEM_FLOATS (64 * KSTR + 64 * VSTR + 128 * PSTR)
#define ATT_SMEM_BYTES  (ATT_SMEM_FLOATS * 4)

__global__ __launch_bounds__(256, 2) void attn_tf32()
{
    extern __shared__ __align__(16) float sm[];
    float* Ks = sm;                       // [64][68]
    float* Vs = sm + 64 * KSTR;           // [64][72]
    float* Ps = sm + 64 * KSTR + 64 * VSTR; // [128][68], also Q staging

    const int tid  = threadIdx.x;
    const int warp = tid >> 5, lane = tid & 31;
    const int grp  = lane >> 2, tig = lane & 3;
    const int wm = warp * 16;             // q-rows [wm, wm+16)

    const int bh = blockIdx.y;
    const int b = bh >> 3, h = bh & 7;
    const int q0 = blockIdx.x * 128;

    const float* qbase = g_qkv + (size_t)b * Nn * 1536 + h * 64;
    const float* kbase = qbase + 512;
    const float* vbase = qbase + 1024;

    // ---- Stage Q tile (128x64, scaled, tf32) into Ps, then lift to registers
    {
        const int lrow = tid >> 1;          // 0..127
        const int lseg = (tid & 1) * 32;    // 0 or 32
        const float* qp = qbase + (size_t)(q0 + lrow) * 1536 + lseg;
        #pragma unroll
        for (int u = 0; u < 8; u++) {
            float4 v = *(const float4*)(qp + u * 4);
            *(float4*)&Ps[lrow * PSTR + lseg + u * 4] = make_float4(
                f2tf(v.x * ATT_SCALE), f2tf(v.y * ATT_SCALE),
                f2tf(v.z * ATT_SCALE), f2tf(v.w * ATT_SCALE));
        }
    }
    __syncthreads();

    float qf[8][4];
    #pragma unroll
    for (int ks = 0; ks < 8; ks++) {
        qf[ks][0] = Ps[(wm + grp) * PSTR + ks * 8 + tig];
        qf[ks][1] = Ps[(wm + grp + 8) * PSTR + ks * 8 + tig];
        qf[ks][2] = Ps[(wm + grp) * PSTR + ks * 8 + tig + 4];
        qf[ks][3] = Ps[(wm + grp + 8) * PSTR + ks * 8 + tig + 4];
    }
    __syncthreads();   // all Q frag reads done before Ps reused for P

    float o[8][4];
    #pragma unroll
    for (int nt = 0; nt < 8; nt++)
        #pragma unroll
        for (int i = 0; i < 4; i++) o[nt][i] = 0.f;

    float m_a = -1e30f, m_b = -1e30f, l_a = 0.f, l_b = 0.f;

    const int lrow2 = tid >> 2;          // 0..63
    const int lseg2 = (tid & 3) * 16;    // 0,16,32,48

    for (int kt = 0; kt < Nn; kt += 64) {
        // ---- Load K, V tiles (tf32-rounded)
        {
            const float* kp = kbase + (size_t)(kt + lrow2) * 1536 + lseg2;
            #pragma unroll
            for (int u = 0; u < 4; u++) {
                float4 v = *(const float4*)(kp + u * 4);
                *(float4*)&Ks[lrow2 * KSTR + lseg2 + u * 4] =
                    make_float4(f2tf(v.x), f2tf(v.y), f2tf(v.z), f2tf(v.w));
            }
            const float* vp = vbase + (size_t)(kt + lrow2) * 1536 + lseg2;
            #pragma unroll
            for (int u = 0; u < 4; u++) {
                float4 v = *(const float4*)(vp + u * 4);
                *(float4*)&Vs[lrow2 * VSTR + lseg2 + u * 4] =
                    make_float4(f2tf(v.x), f2tf(v.y), f2tf(v.z), f2tf(v.w));
            }
        }
        __syncthreads();

        // ---- S = Q K^T  (warp: m16 x n64, k=64) — accumulators in registers
        float sc[8][4];
        #pragma unroll
        for (int nt = 0; nt < 8; nt++)
            #pragma unroll
            for (int i = 0; i < 4; i++) sc[nt][i] = 0.f;

        #pragma unroll
        for (int ks = 0; ks < 8; ks++) {
            #pragma unroll
            for (int nt = 0; nt < 8; nt++) {
                float b0 = Ks[(nt * 8 + grp) * KSTR + ks * 8 + tig];
                float b1 = Ks[(nt * 8 + grp) * KSTR + ks * 8 + tig + 4];
                mma_tf32(sc[nt], qf[ks][0], qf[ks][1], qf[ks][2], qf[ks][3], b0, b1);
            }
        }

        // ---- Online softmax in registers (rows wm+grp and wm+grp+8)
        {
            float mx_a = -1e30f, mx_b = -1e30f;
            #pragma unroll
            for (int nt = 0; nt < 8; nt++) {
                mx_a = fmaxf(mx_a, fmaxf(sc[nt][0], sc[nt][1]));
                mx_b = fmaxf(mx_b, fmaxf(sc[nt][2], sc[nt][3]));
            }
            mx_a = fmaxf(mx_a, __shfl_xor_sync(0xffffffffu, mx_a, 1));
            mx_a = fmaxf(mx_a, __shfl_xor_sync(0xffffffffu, mx_a, 2));
            mx_b = fmaxf(mx_b, __shfl_xor_sync(0xffffffffu, mx_b, 1));
            mx_b = fmaxf(mx_b, __shfl_xor_sync(0xffffffffu, mx_b, 2));

            float mn_a = fmaxf(m_a, mx_a);
            float mn_b = fmaxf(m_b, mx_b);

            float sum_a = 0.f, sum_b = 0.f;
            #pragma unroll
            for (int nt = 0; nt < 8; nt++) {
                sc[nt][0] = __expf(sc[nt][0] - mn_a);
                sc[nt][1] = __expf(sc[nt][1] - mn_a);
                sc[nt][2] = __expf(sc[nt][2] - mn_b);
                sc[nt][3] = __expf(sc[nt][3] - mn_b);
                sum_a += sc[nt][0] + sc[nt][1];
                sum_b += sc[nt][2] + sc[nt][3];
            }
            sum_a += __shfl_xor_sync(0xffffffffu, sum_a, 1);
            sum_a += __shfl_xor_sync(0xffffffffu, sum_a, 2);
            sum_b += __shfl_xor_sync(0xffffffffu, sum_b, 1);
            sum_b += __shfl_xor_sync(0xffffffffu, sum_b, 2);

            float alpha_a = __expf(m_a - mn_a);
            float alpha_b = __expf(m_b - mn_b);
            l_a = l_a * alpha_a + sum_a;
            l_b = l_b * alpha_b + sum_b;
            m_a = mn_a;
            m_b = mn_b;

            #pragma unroll
            for (int nt = 0; nt < 8; nt++) {
                o[nt][0] *= alpha_a; o[nt][1] *= alpha_a;
                o[nt][2] *= alpha_b; o[nt][3] *= alpha_b;
            }
        }

        // ---- Store P (tf32) to this warp's own rows of Ps
        #pragma unroll
        for (int nt = 0; nt < 8; nt++) {
            *(float2*)&Ps[(wm + grp) * PSTR + nt * 8 + tig * 2] =
                make_float2(f2tf(sc[nt][0]), f2tf(sc[nt][1]));
            *(float2*)&Ps[(wm + grp + 8) * PSTR + nt * 8 + tig * 2] =
                make_float2(f2tf(sc[nt][2]), f2tf(sc[nt][3]));
        }
        __syncwarp();   // warp reads only its own 16 rows

        // ---- O += P @ V  (warp: m16 x n64 over d, k=64 keys)
        #pragma unroll
        for (int ks = 0; ks < 8; ks++) {
            float a0 = Ps[(wm + grp) * PSTR + ks * 8 + tig];
            float a1 = Ps[(wm + grp + 8) * PSTR + ks * 8 + tig];
            float a2 = Ps[(wm + grp) * PSTR + ks * 8 + tig + 4];
            float a3 = Ps[(wm + grp + 8) * PSTR + ks * 8 + tig + 4];
            #pragma unroll
            for (int nt = 0; nt < 8; nt++) {
                float b0 = Vs[(ks * 8 + tig) * VSTR + nt * 8 + grp];
                float b1 = Vs[(ks * 8 + tig + 4) * VSTR + nt * 8 + grp];
                mma_tf32(o[nt], a0, a1, a2, a3, b0, b1);
            }
        }
        __syncthreads();   // PV done before next K/V overwrite (and P rows safe)
    }

    // ---- Normalize and write out
    float inv_a = 1.0f / l_a;
    float inv_b = 1.0f / l_b;
    #pragma unroll
    for (int nt = 0; nt < 8; nt++) {
        int col = h * 64 + nt * 8 + tig * 2;
        float* c0 = g_ctx + ((size_t)b * Nn + q0 + wm + grp) * Ee + col;
        *(float2*)c0 = make_float2(o[nt][0] * inv_a, o[nt][1] * inv_a);
        float* c1 = g_ctx + ((size_t)b * Nn + q0 + wm + grp + 8) * Ee + col;
        *(float2*)c1 = make_float2(o[nt][2] * inv_b, o[nt][3] * inv_b);
    }
}

// ============================================================================
// Host launch
// ============================================================================
extern "C" void kernel_launch(void* const* d_in, const int* in_sizes, int n_in,
                              void* d_out, int out_size)
{
    const float* x     = (const float*)d_in[0];
    const float* w_qkv = (const float*)d_in[1];
    const float* b_qkv = (const float*)d_in[2];
    const float* w_out = (const float*)d_in[3];
    const float* b_out = (const float*)d_in[4];
    float* out = (float*)d_out;

    void* qkv_ptr = nullptr;
    void* ctx_ptr = nullptr;
    cudaGetSymbolAddress(&qkv_ptr, g_qkv);
    cudaGetSymbolAddress(&ctx_ptr, g_ctx);
    float* qkv = (float*)qkv_ptr;
    float* ctx = (float*)ctx_ptr;

    cudaFuncSetAttribute(attn_tf32, cudaFuncAttributeMaxDynamicSharedMemorySize,
                         ATT_SMEM_BYTES);

    const int M = Bb * Nn;  // 8192

    // 1) QKV projection
    gemm_tf32<<<dim3(3 * Ee / 128, M / 128), 256>>>(x, w_qkv, b_qkv, qkv,
                                                    M, 3 * Ee, Ee);

    // 2) Attention: 128-query tiles
    attn_tf32<<<dim3(Nn / 128, Bb * Hh), 256, ATT_SMEM_BYTES>>>();

    // 3) Output projection
    gemm_tf32<<<dim3(Ee / 128, M / 128), 256>>>(ctx, w_out, b_out, out,
                                                M, Ee, Ee);
}